// round 9
// baseline (speedup 1.0000x reference)
#include <cuda_runtime.h>
#include <cuda_fp16.h>
#include <cstdint>
#include <cstddef>

#define FD 32
#define HD 64
#define ED 128
#define MT 128
#define TPC 8

#define N_MAX    1600000
#define NSEG_MAX 65536

__device__ int g_count[NSEG_MAX];
__device__ int g_cursor[NSEG_MAX];
__device__ int g_sorted[N_MAX];

// ---------------- smem layout (bytes) ----------------
// X: per-warp interleaved block of 5120B: [32 rows hi @80B][32 rows lo @80B].
//    O staging ([32][33] f32 = 4224B) aliases the warp's X block (disjoint lifetime).
// H : [128 m][k<64] stride 144B (fp16)
// B1: [64 n][k<32]  stride 80B  (W1^T fp16)
// B2: [128 n][k<64] stride 144B (W2^T fp16)
#define XS   80
#define HS   144
#define B1S  80
#define WXB  5120            // per-warp X block size
#define OFF_X    0
#define OFF_H    20480
#define OFF_B1   38912
#define OFF_B2   44032
#define OFF_SB1  62464
#define OFF_SB2  62720
#define OFF_SSEG 63232
#define SMEM_TOTAL 63744
#define O_PITCH  33

__device__ __forceinline__ uint32_t smem_u32_of(const void* p) {
    uint32_t a;
    asm("{ .reg .u64 t; cvta.to.shared.u64 t, %1; cvt.u32.u64 %0, t; }" : "=r"(a) : "l"(p));
    return a;
}
__device__ __forceinline__ void ldsm4(uint32_t* r, uint32_t a) {
    asm volatile("ldmatrix.sync.aligned.m8n8.x4.shared.b16 {%0,%1,%2,%3}, [%4];"
                 : "=r"(r[0]), "=r"(r[1]), "=r"(r[2]), "=r"(r[3]) : "r"(a));
}
__device__ __forceinline__ void mma16816(float* c, const uint32_t* a, uint32_t b0, uint32_t b1) {
    asm volatile("mma.sync.aligned.m16n8k16.row.col.f32.f16.f16.f32 "
                 "{%0,%1,%2,%3}, {%4,%5,%6,%7}, {%8,%9}, {%0,%1,%2,%3};"
                 : "+f"(c[0]), "+f"(c[1]), "+f"(c[2]), "+f"(c[3])
                 : "r"(a[0]), "r"(a[1]), "r"(a[2]), "r"(a[3]), "r"(b0), "r"(b1));
}
__device__ __forceinline__ void sts128(uint32_t a, uint32_t x, uint32_t y, uint32_t z, uint32_t w) {
    asm volatile("st.shared.v4.b32 [%0], {%1,%2,%3,%4};" :: "r"(a), "r"(x), "r"(y), "r"(z), "r"(w) : "memory");
}
__device__ __forceinline__ void split2(float v0, float v1, uint32_t& hi, uint32_t& lo) {
    __half h0 = __float2half_rn(v0);
    __half h1 = __float2half_rn(v1);
    __half l0 = __float2half_rn(v0 - __half2float(h0));
    __half l1 = __float2half_rn(v1 - __half2float(h1));
    __half2 hp = __halves2half2(h0, h1);
    __half2 lp = __halves2half2(l0, l1);
    hi = *reinterpret_cast<uint32_t*>(&hp);
    lo = *reinterpret_cast<uint32_t*>(&lp);
}
__device__ __forceinline__ uint32_t pack2(float v0, float v1) {
    __half2 h = __floats2half2_rn(v0, v1);
    return *reinterpret_cast<uint32_t*>(&h);
}

// ---------------- sort pipeline ----------------

__global__ void zero_and_init(float* __restrict__ out, int out_n, int nseg) {
    int i = blockIdx.x * blockDim.x + threadIdx.x;
    if (i < out_n) out[i] = 0.0f;          // 0-init == isfinite guard for ReLU>=0 maxima
    if (i < nseg) g_count[i] = 0;
}
__global__ void hist_kernel(const int* __restrict__ seg, int n) {
    int i = blockIdx.x * blockDim.x + threadIdx.x;
    if (i < n) atomicAdd(&g_count[seg[i]], 1);
}
__global__ __launch_bounds__(1024) void scan_kernel(int nseg) {
    __shared__ int ssum[1024];
    int t = threadIdx.x;
    int C = (nseg + 1023) >> 10;
    int lo = t * C, hi = min(lo + C, nseg);
    int s = 0;
    for (int i = lo; i < hi; i++) s += g_count[i];
    ssum[t] = s;
    __syncthreads();
    for (int d = 1; d < 1024; d <<= 1) {
        int o = (t >= d) ? ssum[t - d] : 0;
        __syncthreads();
        ssum[t] += o;
        __syncthreads();
    }
    int pre = ssum[t] - s;
    for (int i = lo; i < hi; i++) { int c = g_count[i]; g_cursor[i] = pre; pre += c; }
}
__global__ void scatter_kernel(const int* __restrict__ seg, int n) {
    int i = blockIdx.x * blockDim.x + threadIdx.x;
    if (i < n) { int pos = atomicAdd(&g_cursor[seg[i]], 1); g_sorted[pos] = i; }
}

// ---------------- warp-MMA fused MLP + segment max, 32m warp tiles ----------------

__global__ __launch_bounds__(128) void fused_mlp_segmax_mma(
    const float* __restrict__ X, const int* __restrict__ seg,
    const float* __restrict__ W1, const float* __restrict__ b1,
    const float* __restrict__ W2, const float* __restrict__ b2,
    unsigned* __restrict__ out, int n)
{
    extern __shared__ char smem[];
    const uint32_t su = smem_u32_of(smem);
    int t = threadIdx.x;
    int wid = t >> 5, lane = t & 31;
    int g = lane >> 2, tig = lane & 3;
    int m0 = wid * 32;                                   // warp owns 32 rows

    float* sb1 = (float*)(smem + OFF_SB1);
    float* sb2 = (float*)(smem + OFF_SB2);
    int*   ssg = (int*)(smem + OFF_SSEG);
    const uint32_t xw = su + OFF_X + wid * WXB;          // warp X block (hi @0, lo @2560)
    float* OW = (float*)(smem + OFF_X + wid * WXB);      // O staging aliases X block

    // ---- stage fp16 weights, coalesced (lanes walk n) ----
    for (int e = t; e < FD * HD; e += 128) {             // B1: 64n x 32k
        int nn = e & 63, k = e >> 6;
        *(__half*)(smem + OFF_B1 + nn * B1S + k * 2) = __float2half_rn(W1[k * HD + nn]);
    }
    for (int e = t; e < HD * ED; e += 128) {             // B2: 128n x 64k
        int nn = e & 127, k = e >> 7;
        *(__half*)(smem + OFF_B2 + nn * HS + k * 2) = __float2half_rn(W2[k * ED + nn]);
    }
    if (t < HD) sb1[t] = b1[t];
    if (t < ED) sb2[t] = b2[t];
    __syncthreads();   // the only block barrier

    int a_row = lane & 15;
    int a_koff = (lane >> 4) * 16;
    int b_nrow = (lane & 7) + ((lane >> 4) << 3);
    int b_koff = ((lane >> 3) & 1) * 16;

    int tiles_total = (n + MT - 1) >> 7;

    for (int it = 0; it < TPC; it++) {
        int tile = blockIdx.x * TPC + it;
        if (tile >= tiles_total) break;
        int base = tile << 7;

        // ---- warp-local staging: 32 seg ids + 32 X rows (fp16 hi/lo) ----
        int p = g_sorted[min(base + m0 + lane, n - 1)];
        ssg[m0 + lane] = seg[p];
        {
            const float4* xr = reinterpret_cast<const float4*>(X + (size_t)p * FD);
            uint32_t hw[16], lw[16];
            #pragma unroll
            for (int i = 0; i < 8; i++) {
                float4 v = __ldg(xr + i);
                split2(v.x, v.y, hw[2 * i], lw[2 * i]);
                split2(v.z, v.w, hw[2 * i + 1], lw[2 * i + 1]);
            }
            uint32_t o0 = xw + (uint32_t)(lane * XS);
            #pragma unroll
            for (int q = 0; q < 4; q++) {
                sts128(o0 + 16 * q,        hw[4 * q], hw[4 * q + 1], hw[4 * q + 2], hw[4 * q + 3]);
                sts128(o0 + 2560 + 16 * q, lw[4 * q], lw[4 * q + 1], lw[4 * q + 2], lw[4 * q + 3]);
            }
        }
        __syncwarp();

        // ================ GEMM1: H = relu(X @ W1 + b1), 32m x 64n ================
        float acc1[2][8][4];
        #pragma unroll
        for (int mt = 0; mt < 2; mt++)
            #pragma unroll
            for (int nt = 0; nt < 8; nt++)
                #pragma unroll
                for (int c = 0; c < 4; c++) acc1[mt][nt][c] = 0.f;

        #pragma unroll
        for (int ks = 0; ks < 2; ks++) {
            uint32_t bh[4][4];
            #pragma unroll
            for (int ntp = 0; ntp < 4; ntp++)
                ldsm4(bh[ntp], su + (uint32_t)(OFF_B1 + (16 * ntp + b_nrow) * B1S + ks * 32 + b_koff));
            #pragma unroll
            for (int mt = 0; mt < 2; mt++) {
                uint32_t ah[4], al[4];
                uint32_t ab = xw + (uint32_t)((mt * 16 + a_row) * XS + ks * 32 + a_koff);
                ldsm4(ah, ab);
                ldsm4(al, ab + 2560);
                #pragma unroll
                for (int ntp = 0; ntp < 4; ntp++) {
                    mma16816(acc1[mt][2 * ntp],     ah, bh[ntp][0], bh[ntp][1]);
                    mma16816(acc1[mt][2 * ntp + 1], ah, bh[ntp][2], bh[ntp][3]);
                    mma16816(acc1[mt][2 * ntp],     al, bh[ntp][0], bh[ntp][1]);
                    mma16816(acc1[mt][2 * ntp + 1], al, bh[ntp][2], bh[ntp][3]);
                }
            }
        }

        // ---- H = relu(+b1) -> fp16 into smem (own rows) ----
        #pragma unroll
        for (int mt = 0; mt < 2; mt++)
            #pragma unroll
            for (int nt = 0; nt < 8; nt++) {
                int j = 8 * nt + 2 * tig;
                float bb0 = sb1[j], bb1 = sb1[j + 1];
                int rA = m0 + mt * 16 + g;
                *(uint32_t*)(smem + OFF_H + rA * HS + j * 2) =
                    pack2(fmaxf(acc1[mt][nt][0] + bb0, 0.f), fmaxf(acc1[mt][nt][1] + bb1, 0.f));
                *(uint32_t*)(smem + OFF_H + (rA + 8) * HS + j * 2) =
                    pack2(fmaxf(acc1[mt][nt][2] + bb0, 0.f), fmaxf(acc1[mt][nt][3] + bb1, 0.f));
            }
        __syncwarp();

        // ---- hoist GEMM2 A-fragments (both m-tiles, all ks) ----
        uint32_t Ah[2][4][4];
        #pragma unroll
        for (int mt = 0; mt < 2; mt++)
            #pragma unroll
            for (int ks = 0; ks < 4; ks++)
                ldsm4(Ah[mt][ks],
                      su + (uint32_t)(OFF_H + (m0 + mt * 16 + a_row) * HS + ks * 32 + a_koff));

        // ================ GEMM2 (two 64-col halves) + per-warp epilogue ================
        #pragma unroll 1
        for (int nh = 0; nh < 2; nh++) {
            float acc[2][8][4];
            #pragma unroll
            for (int mt = 0; mt < 2; mt++)
                #pragma unroll
                for (int nt = 0; nt < 8; nt++)
                    #pragma unroll
                    for (int c = 0; c < 4; c++) acc[mt][nt][c] = 0.f;

            #pragma unroll
            for (int ks = 0; ks < 4; ks++)
                #pragma unroll
                for (int ntp = 0; ntp < 4; ntp++) {
                    uint32_t bh[4];
                    ldsm4(bh, su + (uint32_t)(OFF_B2 + (64 * nh + 16 * ntp + b_nrow) * HS + ks * 32 + b_koff));
                    #pragma unroll
                    for (int mt = 0; mt < 2; mt++) {
                        mma16816(acc[mt][2 * ntp],     Ah[mt][ks], bh[0], bh[1]);
                        mma16816(acc[mt][2 * ntp + 1], Ah[mt][ks], bh[2], bh[3]);
                    }
                }

            // per-warp epilogue: 2 passes of 32 cols via O staging (aliased X block)
            #pragma unroll 1
            for (int pp = 0; pp < 2; pp++) {
                __syncwarp();      // previous pass reads (or GEMM1 X reads) complete
                #pragma unroll
                for (int q = 0; q < 4; q++) {
                    int nt = 4 * pp + q;
                    int cl = 8 * q + 2 * tig;
                    int jg = 64 * nh + 32 * pp + cl;
                    float bb0 = sb2[jg], bb1 = sb2[jg + 1];
                    #pragma unroll
                    for (int mt = 0; mt < 2; mt++) {
                        float* rA = OW + (mt * 16 + g) * O_PITCH + cl;
                        rA[0] = fmaxf(acc[mt][nt][0] + bb0, 0.f);
                        rA[1] = fmaxf(acc[mt][nt][1] + bb1, 0.f);
                        float* rB = OW + (mt * 16 + g + 8) * O_PITCH + cl;
                        rB[0] = fmaxf(acc[mt][nt][2] + bb0, 0.f);
                        rB[1] = fmaxf(acc[mt][nt][3] + bb1, 0.f);
                    }
                }
                __syncwarp();
                {   // run-length segment max: lane = 1 col x this warp's 32 sorted rows
                    int j = 64 * nh + 32 * pp + lane;
                    const float* ocol = OW + lane;
                    float rm = 0.f; int cs = -1;
                    #pragma unroll
                    for (int mi = 0; mi < 32; mi++) {
                        int s = ssg[m0 + mi];
                        float v = ocol[mi * O_PITCH];
                        if (s != cs) {
                            if (cs >= 0) {
                                unsigned u = __float_as_uint(rm);  // >=0: bit order == fp order
                                if (u) atomicMax(out + (size_t)cs * ED + j, u);
                            }
                            cs = s; rm = v;
                        } else rm = fmaxf(rm, v);
                    }
                    if (cs >= 0) {
                        unsigned u = __float_as_uint(rm);
                        if (u) atomicMax(out + (size_t)cs * ED + j, u);
                    }
                }
            }
        }
        __syncwarp();   // O/X/H quiesced before next tile restage
    }
}

extern "C" void kernel_launch(void* const* d_in, const int* in_sizes, int n_in,
                              void* d_out, int out_size)
{
    const float* X   = (const float*)d_in[0];
    const int*   seg = (const int*)  d_in[1];
    const float* W1  = (const float*)d_in[2];
    const float* b1  = (const float*)d_in[3];
    const float* W2  = (const float*)d_in[4];
    const float* b2  = (const float*)d_in[5];
    float* out = (float*)d_out;

    int n = in_sizes[1];
    int nseg = out_size / ED;

    cudaFuncSetAttribute(fused_mlp_segmax_mma,
                         cudaFuncAttributeMaxDynamicSharedMemorySize, SMEM_TOTAL);

    int initN = max(out_size, nseg);
    zero_and_init<<<(initN + 255) / 256, 256>>>(out, out_size, nseg);
    hist_kernel<<<(n + 255) / 256, 256>>>(seg, n);
    scan_kernel<<<1, 1024>>>(nseg);
    scatter_kernel<<<(n + 255) / 256, 256>>>(seg, n);

    int tiles = (n + MT - 1) / MT;
    int grid = (tiles + TPC - 1) / TPC;
    fused_mlp_segmax_mma<<<grid, 128, SMEM_TOTAL>>>(X, seg, W1, b1, W2, b2, (unsigned*)out, n);
}

// round 10
// speedup vs baseline: 1.2603x; 1.2603x over previous
#include <cuda_runtime.h>
#include <cuda_fp16.h>
#include <cstdint>
#include <cstddef>

#define FD 32
#define HD 64
#define ED 128
#define MT 128
#define TPC 8

#define N_MAX    1600000
#define NSEG_MAX 65536

__device__ int g_count[NSEG_MAX];
__device__ int g_cursor[NSEG_MAX];
__device__ int g_sorted[N_MAX];

// ---------------- smem layout (bytes) ----------------
//   X  : [128 m][k<32]  stride 80B   (fp16 single)
//   H  : [128 m][k<64]  stride 144B  (fp16 single)
//   B1 : [64 n][k<32]   stride 80B   (W1^T fp16)
//   B2 : [128 n][k<64]  stride 144B  (W2^T fp16)
//   O  : per-warp [16][33] f32 staging
#define XS   80
#define HS   144
#define B1S  80
#define OFF_X    0
#define OFF_H    10240
#define OFF_B1   28672
#define OFF_B2   33792
#define OFF_O    52224
#define OFF_SB1  69120
#define OFF_SB2  69376
#define OFF_SSEG 69888
#define SMEM_TOTAL 70400
#define O_PITCH  33

__device__ __forceinline__ uint32_t smem_u32_of(const void* p) {
    uint32_t a;
    asm("{ .reg .u64 t; cvta.to.shared.u64 t, %1; cvt.u32.u64 %0, t; }" : "=r"(a) : "l"(p));
    return a;
}
__device__ __forceinline__ void ldsm4(uint32_t* r, uint32_t a) {
    asm volatile("ldmatrix.sync.aligned.m8n8.x4.shared.b16 {%0,%1,%2,%3}, [%4];"
                 : "=r"(r[0]), "=r"(r[1]), "=r"(r[2]), "=r"(r[3]) : "r"(a));
}
__device__ __forceinline__ void mma16816(float* c, const uint32_t* a, uint32_t b0, uint32_t b1) {
    asm volatile("mma.sync.aligned.m16n8k16.row.col.f32.f16.f16.f32 "
                 "{%0,%1,%2,%3}, {%4,%5,%6,%7}, {%8,%9}, {%0,%1,%2,%3};"
                 : "+f"(c[0]), "+f"(c[1]), "+f"(c[2]), "+f"(c[3])
                 : "r"(a[0]), "r"(a[1]), "r"(a[2]), "r"(a[3]), "r"(b0), "r"(b1));
}
__device__ __forceinline__ void sts128(uint32_t a, uint32_t x, uint32_t y, uint32_t z, uint32_t w) {
    asm volatile("st.shared.v4.b32 [%0], {%1,%2,%3,%4};" :: "r"(a), "r"(x), "r"(y), "r"(z), "r"(w) : "memory");
}
__device__ __forceinline__ uint32_t pack2(float v0, float v1) {
    __half2 h = __floats2half2_rn(v0, v1);
    return *reinterpret_cast<uint32_t*>(&h);
}

// ---------------- sort pipeline ----------------

__global__ void zero_and_init(float* __restrict__ out, int out_n, int nseg) {
    int i = blockIdx.x * blockDim.x + threadIdx.x;
    if (i < out_n) out[i] = 0.0f;          // 0-init == isfinite guard for ReLU>=0 maxima
    if (i < nseg) g_count[i] = 0;
}
__global__ void hist_kernel(const int* __restrict__ seg, int n) {
    int i = blockIdx.x * blockDim.x + threadIdx.x;
    if (i < n) atomicAdd(&g_count[seg[i]], 1);
}
__global__ __launch_bounds__(1024) void scan_kernel(int nseg) {
    __shared__ int ssum[1024];
    int t = threadIdx.x;
    int C = (nseg + 1023) >> 10;
    int lo = t * C, hi = min(lo + C, nseg);
    int s = 0;
    for (int i = lo; i < hi; i++) s += g_count[i];
    ssum[t] = s;
    __syncthreads();
    for (int d = 1; d < 1024; d <<= 1) {
        int o = (t >= d) ? ssum[t - d] : 0;
        __syncthreads();
        ssum[t] += o;
        __syncthreads();
    }
    int pre = ssum[t] - s;
    for (int i = lo; i < hi; i++) { int c = g_count[i]; g_cursor[i] = pre; pre += c; }
}
__global__ void scatter_kernel(const int* __restrict__ seg, int n) {
    int i = blockIdx.x * blockDim.x + threadIdx.x;
    if (i < n) { int pos = atomicAdd(&g_cursor[seg[i]], 1); g_sorted[pos] = i; }
}

// ---------------- warp-MMA fused MLP + segment max, prefetched gather ----------------

__global__ __launch_bounds__(256, 2) void fused_mlp_segmax_mma(
    const float* __restrict__ X, const int* __restrict__ seg,
    const float* __restrict__ W1, const float* __restrict__ b1,
    const float* __restrict__ W2, const float* __restrict__ b2,
    unsigned* __restrict__ out, int n)
{
    extern __shared__ char smem[];
    const uint32_t su = smem_u32_of(smem);
    int t = threadIdx.x;
    int wid = t >> 5, lane = t & 31;
    int g = lane >> 2, tig = lane & 3;
    int m0 = wid * 16;

    float* sb1 = (float*)(smem + OFF_SB1);
    float* sb2 = (float*)(smem + OFF_SB2);
    int*   ssg = (int*)(smem + OFF_SSEG);
    float* OW  = (float*)(smem + OFF_O) + wid * 16 * O_PITCH;

    // ---- stage fp16 weights, coalesced (lanes walk n) ----
    #pragma unroll
    for (int i = 0; i < 8; i++) {                 // B1: 64n x 32k
        int e = i * 256 + t, nn = e & 63, k = e >> 6;
        *(__half*)(smem + OFF_B1 + nn * B1S + k * 2) = __float2half_rn(W1[k * HD + nn]);
    }
    #pragma unroll
    for (int i = 0; i < 32; i++) {                // B2: 128n x 64k
        int e = i * 256 + t, nn = e & 127, k = e >> 7;
        *(__half*)(smem + OFF_B2 + nn * HS + k * 2) = __float2half_rn(W2[k * ED + nn]);
    }
    if (t < HD) sb1[t] = b1[t];
    if (t < ED) sb2[t] = b2[t];
    __syncthreads();   // the only block barrier

    int a_row = lane & 15;
    int a_koff = (lane >> 4) * 16;
    int b_nrow = (lane & 7) + ((lane >> 4) << 3);
    int b_koff = ((lane >> 3) & 1) * 16;

    int tiles_total = (n + MT - 1) >> 7;
    int mrow = t >> 1, half = t & 1;              // staging assignment (2 thr/row)

    // ---- initial gather prefetch (tile 0 of this CTA) ----
    float4 xv[4];
    int pseg = 0;
    {
        int tile0 = blockIdx.x * TPC;
        if (tile0 < tiles_total) {
            int base0 = tile0 << 7;
            int p = g_sorted[min(base0 + mrow, n - 1)];
            const float4* xr = reinterpret_cast<const float4*>(X + (size_t)p * FD) + half * 4;
            #pragma unroll
            for (int i = 0; i < 4; i++) xv[i] = __ldg(xr + i);
            int ps = g_sorted[min(base0 + m0 + lane, n - 1)];
            pseg = __ldg(seg + ps);
        }
    }

    for (int it = 0; it < TPC; it++) {
        int tile = blockIdx.x * TPC + it;
        if (tile >= tiles_total) break;

        // ---- stage current tile from prefetched registers ----
        if (lane < 16) ssg[m0 + lane] = pseg;
        {
            uint32_t w[8];
            #pragma unroll
            for (int i = 0; i < 4; i++) {
                w[2 * i]     = pack2(xv[i].x, xv[i].y);
                w[2 * i + 1] = pack2(xv[i].z, xv[i].w);
            }
            uint32_t o0 = su + OFF_X + (uint32_t)(mrow * XS + half * 32);
            sts128(o0,      w[0], w[1], w[2], w[3]);
            sts128(o0 + 16, w[4], w[5], w[6], w[7]);
        }

        // ---- issue next tile's gather (latency hidden under GEMMs + epilogue) ----
        {
            int tile1 = tile + 1;
            bool more = (it + 1 < TPC) && (tile1 < tiles_total);
            int base1 = tile1 << 7;
            int ip = more ? min(base1 + mrow, n - 1) : 0;
            int p = g_sorted[ip];
            const float4* xr = reinterpret_cast<const float4*>(X + (size_t)p * FD) + half * 4;
            #pragma unroll
            for (int i = 0; i < 4; i++) xv[i] = __ldg(xr + i);
            int is = more ? min(base1 + m0 + lane, n - 1) : 0;
            int ps = g_sorted[is];
            pseg = __ldg(seg + ps);
        }
        __syncwarp();

        // ================ GEMM1: H = relu(X @ W1 + b1), 16m x 64n ================
        float acc1[8][4];
        #pragma unroll
        for (int nt = 0; nt < 8; nt++)
            #pragma unroll
            for (int c = 0; c < 4; c++) acc1[nt][c] = 0.f;

        #pragma unroll
        for (int ks = 0; ks < 2; ks++) {
            uint32_t ah[4];
            ldsm4(ah, su + (uint32_t)(OFF_X + (m0 + a_row) * XS + ks * 32 + a_koff));
            #pragma unroll
            for (int ntp = 0; ntp < 4; ntp++) {
                uint32_t bh[4];
                ldsm4(bh, su + (uint32_t)(OFF_B1 + (16 * ntp + b_nrow) * B1S + ks * 32 + b_koff));
                mma16816(acc1[2 * ntp],     ah, bh[0], bh[1]);
                mma16816(acc1[2 * ntp + 1], ah, bh[2], bh[3]);
            }
        }

        // ---- H = relu(+b1) -> fp16 into smem (own rows only) ----
        #pragma unroll
        for (int nt = 0; nt < 8; nt++) {
            int j = 8 * nt + 2 * tig;
            float bb0 = sb1[j], bb1 = sb1[j + 1];
            *(uint32_t*)(smem + OFF_H + (m0 + g) * HS + j * 2) =
                pack2(fmaxf(acc1[nt][0] + bb0, 0.f), fmaxf(acc1[nt][1] + bb1, 0.f));
            *(uint32_t*)(smem + OFF_H + (m0 + g + 8) * HS + j * 2) =
                pack2(fmaxf(acc1[nt][2] + bb0, 0.f), fmaxf(acc1[nt][3] + bb1, 0.f));
        }
        __syncwarp();

        // ---- hoist GEMM2 A-fragments (reused for both n-halves) ----
        uint32_t Ah[4][4];
        #pragma unroll
        for (int ks = 0; ks < 4; ks++)
            ldsm4(Ah[ks], su + (uint32_t)(OFF_H + (m0 + a_row) * HS + ks * 32 + a_koff));

        // ================ GEMM2 (two 64-col halves) + per-warp epilogue ================
        #pragma unroll 1
        for (int nh = 0; nh < 2; nh++) {
            float acc[8][4];
            #pragma unroll
            for (int nt = 0; nt < 8; nt++)
                #pragma unroll
                for (int c = 0; c < 4; c++) acc[nt][c] = 0.f;

            #pragma unroll
            for (int ks = 0; ks < 4; ks++)
                #pragma unroll
                for (int ntp = 0; ntp < 4; ntp++) {
                    uint32_t bh[4];
                    ldsm4(bh, su + (uint32_t)(OFF_B2 + (64 * nh + 16 * ntp + b_nrow) * HS + ks * 32 + b_koff));
                    mma16816(acc[2 * ntp],     Ah[ks], bh[0], bh[1]);
                    mma16816(acc[2 * ntp + 1], Ah[ks], bh[2], bh[3]);
                }

            // per-warp epilogue: 2 passes of 32 cols through warp-private O staging
            #pragma unroll 1
            for (int p = 0; p < 2; p++) {
                __syncwarp();
                #pragma unroll
                for (int q = 0; q < 4; q++) {
                    int nt = 4 * p + q;
                    int cl = 8 * q + 2 * tig;
                    int jg = 64 * nh + 32 * p + cl;
                    float bb0 = sb2[jg], bb1 = sb2[jg + 1];
                    float* rA = OW + g * O_PITCH + cl;
                    rA[0] = fmaxf(acc[nt][0] + bb0, 0.f);
                    rA[1] = fmaxf(acc[nt][1] + bb1, 0.f);
                    float* rB = OW + (g + 8) * O_PITCH + cl;
                    rB[0] = fmaxf(acc[nt][2] + bb0, 0.f);
                    rB[1] = fmaxf(acc[nt][3] + bb1, 0.f);
                }
                __syncwarp();
                {   // run-length segment max: lane = 1 col x this warp's 16 sorted rows
                    int j = 64 * nh + 32 * p + lane;
                    const float* ocol = OW + lane;
                    float rm = 0.f; int cs = -1;
                    #pragma unroll
                    for (int mi = 0; mi < 16; mi++) {
                        int s = ssg[m0 + mi];
                        float v = ocol[mi * O_PITCH];
                        if (s != cs) {
                            if (cs >= 0) {
                                unsigned u = __float_as_uint(rm);  // >=0: bit order == fp order
                                if (u) atomicMax(out + (size_t)cs * ED + j, u);
                            }
                            cs = s; rm = v;
                        } else rm = fmaxf(rm, v);
                    }
                    if (cs >= 0) {
                        unsigned u = __float_as_uint(rm);
                        if (u) atomicMax(out + (size_t)cs * ED + j, u);
                    }
                }
            }
        }
        __syncwarp();   // staging regions quiesced before next tile
    }
}

extern "C" void kernel_launch(void* const* d_in, const int* in_sizes, int n_in,
                              void* d_out, int out_size)
{
    const float* X   = (const float*)d_in[0];
    const int*   seg = (const int*)  d_in[1];
    const float* W1  = (const float*)d_in[2];
    const float* b1  = (const float*)d_in[3];
    const float* W2  = (const float*)d_in[4];
    const float* b2  = (const float*)d_in[5];
    float* out = (float*)d_out;

    int n = in_sizes[1];
    int nseg = out_size / ED;

    cudaFuncSetAttribute(fused_mlp_segmax_mma,
                         cudaFuncAttributeMaxDynamicSharedMemorySize, SMEM_TOTAL);

    int initN = max(out_size, nseg);
    zero_and_init<<<(initN + 255) / 256, 256>>>(out, out_size, nseg);
    hist_kernel<<<(n + 255) / 256, 256>>>(seg, n);
    scan_kernel<<<1, 1024>>>(nseg);
    scatter_kernel<<<(n + 255) / 256, 256>>>(seg, n);

    int tiles = (n + MT - 1) / MT;
    int grid = (tiles + TPC - 1) / TPC;
    fused_mlp_segmax_mma<<<grid, 256, SMEM_TOTAL>>>(X, seg, W1, b1, W2, b2, (unsigned*)out, n);
}

// round 13
// speedup vs baseline: 1.2836x; 1.0185x over previous
#include <cuda_runtime.h>
#include <cuda_fp16.h>
#include <cstdint>
#include <cstddef>

#define FD 32
#define HD 64
#define ED 128
#define MT 128
#define TPC 8

#define N_MAX    1600000
#define NSEG_MAX 65536

__device__ int g_count[NSEG_MAX];
__device__ int g_cursor[NSEG_MAX];
__device__ int g_sorted[N_MAX];

// ---------------- smem layout (bytes) ----------------
//   X  : [128 m][k<32]  stride 80B   (fp16)
//   B1 : [64 n][k<32]   stride 80B   (W1^T fp16)
//   B2 : [128 n][k<64]  stride 144B  (W2^T fp16)
//   O  : per-warp [16][33] f32 staging
// (H tile eliminated: GEMM1 C-fragments are converted in registers directly
//  into GEMM2 A-fragments — identical thread-data mapping.)
#define XS   80
#define HS   144
#define B1S  80
#define OFF_X    0
#define OFF_B1   10240
#define OFF_B2   15360
#define OFF_O    33792
#define OFF_SB1  50688
#define OFF_SB2  50944
#define OFF_SSEG 51456
#define SMEM_TOTAL 51968
#define O_PITCH  33

__device__ __forceinline__ uint32_t smem_u32_of(const void* p) {
    uint32_t a;
    asm("{ .reg .u64 t; cvta.to.shared.u64 t, %1; cvt.u32.u64 %0, t; }" : "=r"(a) : "l"(p));
    return a;
}
__device__ __forceinline__ void ldsm4(uint32_t* r, uint32_t a) {
    asm volatile("ldmatrix.sync.aligned.m8n8.x4.shared.b16 {%0,%1,%2,%3}, [%4];"
                 : "=r"(r[0]), "=r"(r[1]), "=r"(r[2]), "=r"(r[3]) : "r"(a));
}
__device__ __forceinline__ void mma16816(float* c, const uint32_t* a, uint32_t b0, uint32_t b1) {
    asm volatile("mma.sync.aligned.m16n8k16.row.col.f32.f16.f16.f32 "
                 "{%0,%1,%2,%3}, {%4,%5,%6,%7}, {%8,%9}, {%0,%1,%2,%3};"
                 : "+f"(c[0]), "+f"(c[1]), "+f"(c[2]), "+f"(c[3])
                 : "r"(a[0]), "r"(a[1]), "r"(a[2]), "r"(a[3]), "r"(b0), "r"(b1));
}
__device__ __forceinline__ void sts128(uint32_t a, uint32_t x, uint32_t y, uint32_t z, uint32_t w) {
    asm volatile("st.shared.v4.b32 [%0], {%1,%2,%3,%4};" :: "r"(a), "r"(x), "r"(y), "r"(z), "r"(w) : "memory");
}
__device__ __forceinline__ uint32_t pack2(float v0, float v1) {
    __half2 h = __floats2half2_rn(v0, v1);
    return *reinterpret_cast<uint32_t*>(&h);
}

// ---------------- sort pipeline ----------------

__global__ void zero_and_init(float* __restrict__ out, int out_n, int nseg) {
    int i = blockIdx.x * blockDim.x + threadIdx.x;
    if (i < out_n) out[i] = 0.0f;          // 0-init == isfinite guard for ReLU>=0 maxima
    if (i < nseg) g_count[i] = 0;
}
__global__ void hist_kernel(const int* __restrict__ seg, int n) {
    int i = blockIdx.x * blockDim.x + threadIdx.x;
    if (i < n) atomicAdd(&g_count[seg[i]], 1);
}
__global__ __launch_bounds__(1024) void scan_kernel(int nseg) {
    __shared__ int ssum[1024];
    int t = threadIdx.x;
    int C = (nseg + 1023) >> 10;
    int lo = t * C, hi = min(lo + C, nseg);
    int s = 0;
    for (int i = lo; i < hi; i++) s += g_count[i];
    ssum[t] = s;
    __syncthreads();
    for (int d = 1; d < 1024; d <<= 1) {
        int o = (t >= d) ? ssum[t - d] : 0;
        __syncthreads();
        ssum[t] += o;
        __syncthreads();
    }
    int pre = ssum[t] - s;
    for (int i = lo; i < hi; i++) { int c = g_count[i]; g_cursor[i] = pre; pre += c; }
}
__global__ void scatter_kernel(const int* __restrict__ seg, int n) {
    int i = blockIdx.x * blockDim.x + threadIdx.x;
    if (i < n) { int pos = atomicAdd(&g_cursor[seg[i]], 1); g_sorted[pos] = i; }
}

// ---------------- warp-MMA fused MLP + segment max ----------------

__global__ __launch_bounds__(256, 2) void fused_mlp_segmax_mma(
    const float* __restrict__ X, const int* __restrict__ seg,
    const float* __restrict__ W1, const float* __restrict__ b1,
    const float* __restrict__ W2, const float* __restrict__ b2,
    unsigned* __restrict__ out, int n)
{
    extern __shared__ char smem[];
    const uint32_t su = smem_u32_of(smem);
    int t = threadIdx.x;
    int wid = t >> 5, lane = t & 31;
    int g = lane >> 2, tig = lane & 3;
    int m0 = wid * 16;

    float* sb1 = (float*)(smem + OFF_SB1);
    float* sb2 = (float*)(smem + OFF_SB2);
    int*   ssg = (int*)(smem + OFF_SSEG);
    float* OW  = (float*)(smem + OFF_O) + wid * 16 * O_PITCH;

    // ---- stage fp16 weights, coalesced (lanes walk n) ----
    #pragma unroll
    for (int i = 0; i < 8; i++) {                 // B1: 64n x 32k
        int e = i * 256 + t, nn = e & 63, k = e >> 6;
        *(__half*)(smem + OFF_B1 + nn * B1S + k * 2) = __float2half_rn(W1[k * HD + nn]);
    }
    #pragma unroll
    for (int i = 0; i < 32; i++) {                // B2: 128n x 64k
        int e = i * 256 + t, nn = e & 127, k = e >> 7;
        *(__half*)(smem + OFF_B2 + nn * HS + k * 2) = __float2half_rn(W2[k * ED + nn]);
    }
    if (t < HD) sb1[t] = b1[t];
    if (t < ED) sb2[t] = b2[t];
    __syncthreads();   // the only block barrier

    int a_row = lane & 15;
    int a_koff = (lane >> 4) * 16;
    int b_nrow = (lane & 7) + ((lane >> 4) << 3);
    int b_koff = ((lane >> 3) & 1) * 16;

    int tiles_total = (n + MT - 1) >> 7;
    int mrow = t >> 1, half = t & 1;              // staging assignment (2 thr/row)

    // ---- initial gather prefetch (tile 0 of this CTA) ----
    float4 xv[4];
    int pseg = 0;
    {
        int tile0 = blockIdx.x * TPC;
        if (tile0 < tiles_total) {
            int base0 = tile0 << 7;
            int p = g_sorted[min(base0 + mrow, n - 1)];
            const float4* xr = reinterpret_cast<const float4*>(X + (size_t)p * FD) + half * 4;
            #pragma unroll
            for (int i = 0; i < 4; i++) xv[i] = __ldg(xr + i);
            int ps = g_sorted[min(base0 + m0 + lane, n - 1)];
            pseg = __ldg(seg + ps);
        }
    }

    for (int it = 0; it < TPC; it++) {
        int tile = blockIdx.x * TPC + it;
        if (tile >= tiles_total) break;

        // ---- stage current tile from prefetched registers ----
        if (lane < 16) ssg[m0 + lane] = pseg;
        {
            uint32_t w[8];
            #pragma unroll
            for (int i = 0; i < 4; i++) {
                w[2 * i]     = pack2(xv[i].x, xv[i].y);
                w[2 * i + 1] = pack2(xv[i].z, xv[i].w);
            }
            uint32_t o0 = su + OFF_X + (uint32_t)(mrow * XS + half * 32);
            sts128(o0,      w[0], w[1], w[2], w[3]);
            sts128(o0 + 16, w[4], w[5], w[6], w[7]);
        }

        // ---- issue next tile's gather (latency hidden under GEMMs + epilogue) ----
        {
            int tile1 = tile + 1;
            bool more = (it + 1 < TPC) && (tile1 < tiles_total);
            int base1 = tile1 << 7;
            int ip = more ? min(base1 + mrow, n - 1) : 0;
            int p = g_sorted[ip];
            const float4* xr = reinterpret_cast<const float4*>(X + (size_t)p * FD) + half * 4;
            #pragma unroll
            for (int i = 0; i < 4; i++) xv[i] = __ldg(xr + i);
            int is = more ? min(base1 + m0 + lane, n - 1) : 0;
            int ps = g_sorted[is];
            pseg = __ldg(seg + ps);
        }
        __syncwarp();

        // ================ GEMM1: H = relu(X @ W1 + b1), 16m x 64n ================
        float acc1[8][4];
        #pragma unroll
        for (int nt = 0; nt < 8; nt++)
            #pragma unroll
            for (int c = 0; c < 4; c++) acc1[nt][c] = 0.f;

        #pragma unroll
        for (int ks = 0; ks < 2; ks++) {
            uint32_t ah[4];
            ldsm4(ah, su + (uint32_t)(OFF_X + (m0 + a_row) * XS + ks * 32 + a_koff));
            #pragma unroll
            for (int ntp = 0; ntp < 4; ntp++) {
                uint32_t bh[4];
                ldsm4(bh, su + (uint32_t)(OFF_B1 + (16 * ntp + b_nrow) * B1S + ks * 32 + b_koff));
                mma16816(acc1[2 * ntp],     ah, bh[0], bh[1]);
                mma16816(acc1[2 * ntp + 1], ah, bh[2], bh[3]);
            }
        }

        // ---- H: bias+ReLU+fp16 directly in registers: C-fragments of GEMM1
        //      ARE the A-fragments of GEMM2 (identical thread-data mapping).
        //      C of n-tile nt covers cols 8nt..8nt+7 = k-range of A k-block nt/2. ----
        uint32_t Ah[4][4];
        #pragma unroll
        for (int kb = 0; kb < 4; kb++) {
            #pragma unroll
            for (int h = 0; h < 2; h++) {
                int nt = 2 * kb + h;
                int j = 8 * nt + 2 * tig;
                float bb0 = sb1[j], bb1 = sb1[j + 1];
                Ah[kb][2 * h] =
                    pack2(fmaxf(acc1[nt][0] + bb0, 0.f), fmaxf(acc1[nt][1] + bb1, 0.f));
                Ah[kb][2 * h + 1] =
                    pack2(fmaxf(acc1[nt][2] + bb0, 0.f), fmaxf(acc1[nt][3] + bb1, 0.f));
            }
        }

        // ================ GEMM2 (two 64-col halves) + per-warp epilogue ================
        #pragma unroll 1
        for (int nh = 0; nh < 2; nh++) {
            float acc[8][4];
            #pragma unroll
            for (int nt = 0; nt < 8; nt++)
                #pragma unroll
                for (int c = 0; c < 4; c++) acc[nt][c] = 0.f;

            #pragma unroll
            for (int ks = 0; ks < 4; ks++)
                #pragma unroll
                for (int ntp = 0; ntp < 4; ntp++) {
                    uint32_t bh[4];
                    ldsm4(bh, su + (uint32_t)(OFF_B2 + (64 * nh + 16 * ntp + b_nrow) * HS + ks * 32 + b_koff));
                    mma16816(acc[2 * ntp],     Ah[ks], bh[0], bh[1]);
                    mma16816(acc[2 * ntp + 1], Ah[ks], bh[2], bh[3]);
                }

            // per-warp epilogue: 2 passes of 32 cols through warp-private O staging
            #pragma unroll 1
            for (int p = 0; p < 2; p++) {
                __syncwarp();
                #pragma unroll
                for (int q = 0; q < 4; q++) {
                    int nt = 4 * p + q;
                    int cl = 8 * q + 2 * tig;
                    int jg = 64 * nh + 32 * p + cl;
                    float bb0 = sb2[jg], bb1 = sb2[jg + 1];
                    float* rA = OW + g * O_PITCH + cl;
                    rA[0] = fmaxf(acc[nt][0] + bb0, 0.f);
                    rA[1] = fmaxf(acc[nt][1] + bb1, 0.f);
                    float* rB = OW + (g + 8) * O_PITCH + cl;
                    rB[0] = fmaxf(acc[nt][2] + bb0, 0.f);
                    rB[1] = fmaxf(acc[nt][3] + bb1, 0.f);
                }
                __syncwarp();
                {   // run-length segment max: lane = 1 col x this warp's 16 sorted rows
                    int j = 64 * nh + 32 * p + lane;
                    const float* ocol = OW + lane;
                    float rm = 0.f; int cs = -1;
                    #pragma unroll
                    for (int mi = 0; mi < 16; mi++) {
                        int s = ssg[m0 + mi];
                        float v = ocol[mi * O_PITCH];
                        if (s != cs) {
                            if (cs >= 0) {
                                unsigned u = __float_as_uint(rm);  // >=0: bit order == fp order
                                if (u) atomicMax(out + (size_t)cs * ED + j, u);
                            }
                            cs = s; rm = v;
                        } else rm = fmaxf(rm, v);
                    }
                    if (cs >= 0) {
                        unsigned u = __float_as_uint(rm);
                        if (u) atomicMax(out + (size_t)cs * ED + j, u);
                    }
                }
            }
        }
        __syncwarp();   // staging regions quiesced before next tile
    }
}

extern "C" void kernel_launch(void* const* d_in, const int* in_sizes, int n_in,
                              void* d_out, int out_size)
{
    const float* X   = (const float*)d_in[0];
    const int*   seg = (const int*)  d_in[1];
    const float* W1  = (const float*)d_in[2];
    const float* b1  = (const float*)d_in[3];
    const float* W2  = (const float*)d_in[4];
    const float* b2  = (const float*)d_in[5];
    float* out = (float*)d_out;

    int n = in_sizes[1];
    int nseg = out_size / ED;

    cudaFuncSetAttribute(fused_mlp_segmax_mma,
                         cudaFuncAttributeMaxDynamicSharedMemorySize, SMEM_TOTAL);

    int initN = max(out_size, nseg);
    zero_and_init<<<(initN + 255) / 256, 256>>>(out, out_size, nseg);
    hist_kernel<<<(n + 255) / 256, 256>>>(seg, n);
    scan_kernel<<<1, 1024>>>(nseg);
    scatter_kernel<<<(n + 255) / 256, 256>>>(seg, n);

    int tiles = (n + MT - 1) / MT;
    int grid = (tiles + TPC - 1) / TPC;
    fused_mlp_segmax_mma<<<grid, 256, SMEM_TOTAL>>>(X, seg, W1, b1, W2, b2, (unsigned*)out, n);
}

// round 14
// speedup vs baseline: 1.9089x; 1.4871x over previous
#include <cuda_runtime.h>
#include <cuda_fp16.h>
#include <cstdint>
#include <cstddef>

#define FD 32
#define HD 64
#define ED 128
#define MT 128
#define TPC 8

#define N_MAX    1600000
#define NSEG_MAX 65536

__device__ int g_count[NSEG_MAX];
__device__ int g_cursor[NSEG_MAX];
__device__ int g_sorted[N_MAX];

// ---------------- smem layout (bytes) ----------------
//   X  : [128 m][k<32]  stride 80B   (fp16)
//   B1 : [64 n][k<32]   stride 80B   (W1^T fp16)
//   B2 : [128 n][k<64]  stride 144B  (W2^T fp16)
// (H eliminated: GEMM1 C-frags become GEMM2 A-frags in registers.
//  O staging + ssg eliminated: epilogue reduces fragments via shfl butterflies.)
#define XS   80
#define HS   144
#define B1S  80
#define OFF_X    0
#define OFF_B1   10240
#define OFF_B2   15360
#define OFF_SB1  33792
#define OFF_SB2  34048
#define SMEM_TOTAL 34560

__device__ __forceinline__ uint32_t smem_u32_of(const void* p) {
    uint32_t a;
    asm("{ .reg .u64 t; cvta.to.shared.u64 t, %1; cvt.u32.u64 %0, t; }" : "=r"(a) : "l"(p));
    return a;
}
__device__ __forceinline__ void ldsm4(uint32_t* r, uint32_t a) {
    asm volatile("ldmatrix.sync.aligned.m8n8.x4.shared.b16 {%0,%1,%2,%3}, [%4];"
                 : "=r"(r[0]), "=r"(r[1]), "=r"(r[2]), "=r"(r[3]) : "r"(a));
}
__device__ __forceinline__ void mma16816(float* c, const uint32_t* a, uint32_t b0, uint32_t b1) {
    asm volatile("mma.sync.aligned.m16n8k16.row.col.f32.f16.f16.f32 "
                 "{%0,%1,%2,%3}, {%4,%5,%6,%7}, {%8,%9}, {%0,%1,%2,%3};"
                 : "+f"(c[0]), "+f"(c[1]), "+f"(c[2]), "+f"(c[3])
                 : "r"(a[0]), "r"(a[1]), "r"(a[2]), "r"(a[3]), "r"(b0), "r"(b1));
}
__device__ __forceinline__ void sts128(uint32_t a, uint32_t x, uint32_t y, uint32_t z, uint32_t w) {
    asm volatile("st.shared.v4.b32 [%0], {%1,%2,%3,%4};" :: "r"(a), "r"(x), "r"(y), "r"(z), "r"(w) : "memory");
}
__device__ __forceinline__ uint32_t pack2(float v0, float v1) {
    __half2 h = __floats2half2_rn(v0, v1);
    return *reinterpret_cast<uint32_t*>(&h);
}

// ---------------- sort pipeline ----------------

__global__ void zero_and_init(float* __restrict__ out, int out_n, int nseg) {
    int i = blockIdx.x * blockDim.x + threadIdx.x;
    if (i < out_n) out[i] = 0.0f;          // 0-init == isfinite guard for ReLU>=0 maxima
    if (i < nseg) g_count[i] = 0;
}
__global__ void hist_kernel(const int* __restrict__ seg, int n) {
    int i = blockIdx.x * blockDim.x + threadIdx.x;
    if (i < n) atomicAdd(&g_count[seg[i]], 1);
}
__global__ __launch_bounds__(1024) void scan_kernel(int nseg) {
    __shared__ int ssum[1024];
    int t = threadIdx.x;
    int C = (nseg + 1023) >> 10;
    int lo = t * C, hi = min(lo + C, nseg);
    int s = 0;
    for (int i = lo; i < hi; i++) s += g_count[i];
    ssum[t] = s;
    __syncthreads();
    for (int d = 1; d < 1024; d <<= 1) {
        int o = (t >= d) ? ssum[t - d] : 0;
        __syncthreads();
        ssum[t] += o;
        __syncthreads();
    }
    int pre = ssum[t] - s;
    for (int i = lo; i < hi; i++) { int c = g_count[i]; g_cursor[i] = pre; pre += c; }
}
__global__ void scatter_kernel(const int* __restrict__ seg, int n) {
    int i = blockIdx.x * blockDim.x + threadIdx.x;
    if (i < n) { int pos = atomicAdd(&g_cursor[seg[i]], 1); g_sorted[pos] = i; }
}

// ---------------- warp-MMA fused MLP + fragment-space segment max ----------------

__global__ __launch_bounds__(256, 2) void fused_mlp_segmax_mma(
    const float* __restrict__ X, const int* __restrict__ seg,
    const float* __restrict__ W1, const float* __restrict__ b1,
    const float* __restrict__ W2, const float* __restrict__ b2,
    unsigned* __restrict__ out, int n)
{
    extern __shared__ char smem[];
    const uint32_t su = smem_u32_of(smem);
    int t = threadIdx.x;
    int wid = t >> 5, lane = t & 31;
    int g = lane >> 2, tig = lane & 3;
    int m0 = wid * 16;

    float* sb1 = (float*)(smem + OFF_SB1);
    float* sb2 = (float*)(smem + OFF_SB2);

    // ---- stage fp16 weights, coalesced (lanes walk n) ----
    #pragma unroll
    for (int i = 0; i < 8; i++) {                 // B1: 64n x 32k
        int e = i * 256 + t, nn = e & 63, k = e >> 6;
        *(__half*)(smem + OFF_B1 + nn * B1S + k * 2) = __float2half_rn(W1[k * HD + nn]);
    }
    #pragma unroll
    for (int i = 0; i < 32; i++) {                // B2: 128n x 64k
        int e = i * 256 + t, nn = e & 127, k = e >> 7;
        *(__half*)(smem + OFF_B2 + nn * HS + k * 2) = __float2half_rn(W2[k * ED + nn]);
    }
    if (t < HD) sb1[t] = b1[t];
    if (t < ED) sb2[t] = b2[t];
    __syncthreads();   // the only block barrier

    int a_row = lane & 15;
    int a_koff = (lane >> 4) * 16;
    int b_nrow = (lane & 7) + ((lane >> 4) << 3);
    int b_koff = ((lane >> 3) & 1) * 16;

    int tiles_total = (n + MT - 1) >> 7;
    int mrow = t >> 1, half = t & 1;              // staging assignment (2 thr/row)

    // ---- initial gather prefetch (tile 0 of this CTA) ----
    float4 xv[4];
    int pseg = 0;
    {
        int tile0 = blockIdx.x * TPC;
        if (tile0 < tiles_total) {
            int base0 = tile0 << 7;
            int p = g_sorted[min(base0 + mrow, n - 1)];
            const float4* xr = reinterpret_cast<const float4*>(X + (size_t)p * FD) + half * 4;
            #pragma unroll
            for (int i = 0; i < 4; i++) xv[i] = __ldg(xr + i);
            int ps = g_sorted[min(base0 + m0 + lane, n - 1)];
            pseg = __ldg(seg + ps);
        }
    }

    for (int it = 0; it < TPC; it++) {
        int tile = blockIdx.x * TPC + it;
        if (tile >= tiles_total) break;

        // ---- keep this tile's seg ids in registers; compute run-boundary mask ----
        int segv = pseg;                           // lane l: seg of row m0+l (lanes 0..15 used)
        int prev = __shfl_up_sync(0xffffffffu, segv, 1);
        unsigned bmask = __ballot_sync(0xffffffffu,
                                       (lane > 0) && (lane < 16) && (segv != prev));

        // ---- stage current tile X from prefetched registers ----
        {
            uint32_t w[8];
            #pragma unroll
            for (int i = 0; i < 4; i++) {
                w[2 * i]     = pack2(xv[i].x, xv[i].y);
                w[2 * i + 1] = pack2(xv[i].z, xv[i].w);
            }
            uint32_t o0 = su + OFF_X + (uint32_t)(mrow * XS + half * 32);
            sts128(o0,      w[0], w[1], w[2], w[3]);
            sts128(o0 + 16, w[4], w[5], w[6], w[7]);
        }

        // ---- issue next tile's gather (latency hidden under GEMMs + epilogue) ----
        {
            int tile1 = tile + 1;
            bool more = (it + 1 < TPC) && (tile1 < tiles_total);
            int base1 = tile1 << 7;
            int ip = more ? min(base1 + mrow, n - 1) : 0;
            int p = g_sorted[ip];
            const float4* xr = reinterpret_cast<const float4*>(X + (size_t)p * FD) + half * 4;
            #pragma unroll
            for (int i = 0; i < 4; i++) xv[i] = __ldg(xr + i);
            int is = more ? min(base1 + m0 + lane, n - 1) : 0;
            int ps = g_sorted[is];
            pseg = __ldg(seg + ps);
        }
        __syncwarp();

        // ================ GEMM1: H = relu(X @ W1 + b1), 16m x 64n ================
        float acc1[8][4];
        #pragma unroll
        for (int nt = 0; nt < 8; nt++)
            #pragma unroll
            for (int c = 0; c < 4; c++) acc1[nt][c] = 0.f;

        #pragma unroll
        for (int ks = 0; ks < 2; ks++) {
            uint32_t ah[4];
            ldsm4(ah, su + (uint32_t)(OFF_X + (m0 + a_row) * XS + ks * 32 + a_koff));
            #pragma unroll
            for (int ntp = 0; ntp < 4; ntp++) {
                uint32_t bh[4];
                ldsm4(bh, su + (uint32_t)(OFF_B1 + (16 * ntp + b_nrow) * B1S + ks * 32 + b_koff));
                mma16816(acc1[2 * ntp],     ah, bh[0], bh[1]);
                mma16816(acc1[2 * ntp + 1], ah, bh[2], bh[3]);
            }
        }

        // ---- H: bias+ReLU+fp16 in registers; GEMM1 C-frags == GEMM2 A-frags ----
        uint32_t Ah[4][4];
        #pragma unroll
        for (int kb = 0; kb < 4; kb++) {
            #pragma unroll
            for (int h = 0; h < 2; h++) {
                int nt = 2 * kb + h;
                int j = 8 * nt + 2 * tig;
                float bb0 = sb1[j], bb1 = sb1[j + 1];
                Ah[kb][2 * h] =
                    pack2(fmaxf(acc1[nt][0] + bb0, 0.f), fmaxf(acc1[nt][1] + bb1, 0.f));
                Ah[kb][2 * h + 1] =
                    pack2(fmaxf(acc1[nt][2] + bb0, 0.f), fmaxf(acc1[nt][3] + bb1, 0.f));
            }
        }

        // ================ GEMM2 (two 64-col halves) + fragment-space epilogue ================
        #pragma unroll 1
        for (int nh = 0; nh < 2; nh++) {
            float acc[8][4];
            #pragma unroll
            for (int nt = 0; nt < 8; nt++)
                #pragma unroll
                for (int c = 0; c < 4; c++) acc[nt][c] = 0.f;

            #pragma unroll
            for (int ks = 0; ks < 4; ks++)
                #pragma unroll
                for (int ntp = 0; ntp < 4; ntp++) {
                    uint32_t bh[4];
                    ldsm4(bh, su + (uint32_t)(OFF_B2 + (64 * nh + 16 * ntp + b_nrow) * HS + ks * 32 + b_koff));
                    mma16816(acc[2 * ntp],     Ah[ks], bh[0], bh[1]);
                    mma16816(acc[2 * ntp + 1], Ah[ks], bh[2], bh[3]);
                }

            // bias + ReLU in place
            #pragma unroll
            for (int nt = 0; nt < 8; nt++) {
                int j = 64 * nh + 8 * nt + 2 * tig;
                float bb0 = sb2[j], bb1 = sb2[j + 1];
                acc[nt][0] = fmaxf(acc[nt][0] + bb0, 0.f);
                acc[nt][1] = fmaxf(acc[nt][1] + bb1, 0.f);
                acc[nt][2] = fmaxf(acc[nt][2] + bb0, 0.f);
                acc[nt][3] = fmaxf(acc[nt][3] + bb1, 0.f);
            }

            // per-run shuffle-butterfly max over rows, atomics from lane g==nt
            int start = 0;
            while (start < 16) {
                unsigned hi = bmask & (0xFFFFFFFFu << (start + 1));
                int nb = hi ? (__ffs(hi) - 1) : 16;
                int rseg = __shfl_sync(0xffffffffu, segv, start);
                bool inLo = (g >= start) && (g < nb);         // row m0+g
                bool inHi = (g + 8 >= start) && (g + 8 < nb); // row m0+g+8
                float va0 = 0.f, va1 = 0.f;
                #pragma unroll
                for (int nt = 0; nt < 8; nt++) {
                    float a0 = fmaxf(inLo ? acc[nt][0] : 0.f, inHi ? acc[nt][2] : 0.f);
                    float a1 = fmaxf(inLo ? acc[nt][1] : 0.f, inHi ? acc[nt][3] : 0.f);
                    a0 = fmaxf(a0, __shfl_xor_sync(0xffffffffu, a0, 4));
                    a1 = fmaxf(a1, __shfl_xor_sync(0xffffffffu, a1, 4));
                    a0 = fmaxf(a0, __shfl_xor_sync(0xffffffffu, a0, 8));
                    a1 = fmaxf(a1, __shfl_xor_sync(0xffffffffu, a1, 8));
                    a0 = fmaxf(a0, __shfl_xor_sync(0xffffffffu, a0, 16));
                    a1 = fmaxf(a1, __shfl_xor_sync(0xffffffffu, a1, 16));
                    if (g == nt) { va0 = a0; va1 = a1; }
                }
                unsigned* ob = out + (size_t)rseg * ED + 64 * nh + 8 * g + 2 * tig;
                unsigned u0 = __float_as_uint(va0);   // >=0: bit order == fp order
                unsigned u1 = __float_as_uint(va1);
                if (u0) atomicMax(ob, u0);
                if (u1) atomicMax(ob + 1, u1);
                start = nb;
            }
        }
        __syncwarp();   // X region quiesced before next tile restage
    }
}

extern "C" void kernel_launch(void* const* d_in, const int* in_sizes, int n_in,
                              void* d_out, int out_size)
{
    const float* X   = (const float*)d_in[0];
    const int*   seg = (const int*)  d_in[1];
    const float* W1  = (const float*)d_in[2];
    const float* b1  = (const float*)d_in[3];
    const float* W2  = (const float*)d_in[4];
    const float* b2  = (const float*)d_in[5];
    float* out = (float*)d_out;

    int n = in_sizes[1];
    int nseg = out_size / ED;

    cudaFuncSetAttribute(fused_mlp_segmax_mma,
                         cudaFuncAttributeMaxDynamicSharedMemorySize, SMEM_TOTAL);

    int initN = max(out_size, nseg);
    zero_and_init<<<(initN + 255) / 256, 256>>>(out, out_size, nseg);
    hist_kernel<<<(n + 255) / 256, 256>>>(seg, n);
    scan_kernel<<<1, 1024>>>(nseg);
    scatter_kernel<<<(n + 255) / 256, 256>>>(seg, n);

    int tiles = (n + MT - 1) / MT;
    int grid = (tiles + TPC - 1) / TPC;
    fused_mlp_segmax_mma<<<grid, 256, SMEM_TOTAL>>>(X, seg, W1, b1, W2, b2, (unsigned*)out, n);
}